// round 1
// baseline (speedup 1.0000x reference)
#include <cuda_runtime.h>

// ---------------------------------------------------------------------------
// MultiGVPConvLayer fused implementation.
//   Inputs (metadata order):
//   0 node_s [N,128] 1 node_v [N,16,3] 2 edge_index [2,E] int32
//   3 edge_s [E,32]  4 edge_v [E,1,3]
//   5 ln_g[128] 6 ln_b[128]
//   7 wes[128,32] 8 bes[128] 9 wev[48,3] 10 bev[48]
//   11 wns[128,128] 12 bns[128] 13 wnv[48,48] 14 bnv[48]
//   15 wrs[128,128] 16 brs[128] 17 wrv[48,48] 18 brv[48]
//   Output: concat( out_s [N,128], out_v [N,48] ) float32
// ---------------------------------------------------------------------------

#define NMAX 50000
#define TE 64

// scratch (static device globals: no runtime allocation allowed)
__device__ float g_agg[(size_t)NMAX * 176];   // per-node [128 scalar | 48 vector] accumulators
__device__ float g_cnt[NMAX];                 // in-degree counts
__device__ float g_wesT[32 * 128];            // wes transposed  [k][out]
__device__ float g_wST[128 * 256];            // [k][ wns_out(128) | wrs_out(128) ]
__device__ float g_wVT[48 * 96];              // [k][ wnv_out(48) | wrv_out(48) ]

__device__ __forceinline__ float sigf(float x) { return 1.f / (1.f + __expf(-x)); }

__device__ __forceinline__ void red4(float* p, float4 v) {
    asm volatile("red.global.add.v4.f32 [%0], {%1,%2,%3,%4};"
                 :: "l"(p), "f"(v.x), "f"(v.y), "f"(v.z), "f"(v.w) : "memory");
}

// ---------------------------------------------------------------------------
// Weight pre-transpose (runs every launch; trivial cost)
// ---------------------------------------------------------------------------
__global__ void prep_kernel(const float* __restrict__ wes,
                            const float* __restrict__ wns, const float* __restrict__ wrs,
                            const float* __restrict__ wnv, const float* __restrict__ wrv)
{
    int t = blockIdx.x * 256 + threadIdx.x;
    if (t < 128 * 32) { int o = t >> 5, k = t & 31;  g_wesT[k * 128 + o] = wes[t]; }
    if (t < 128 * 128){ int o = t >> 7, k = t & 127; g_wST[k * 256 + o] = wns[t];
                                                     g_wST[k * 256 + 128 + o] = wrs[t]; }
    if (t < 48 * 48)  { int o = t / 48, k = t % 48;  g_wVT[k * 96 + o] = wnv[t];
                                                     g_wVT[k * 96 + 48 + o] = wrv[t]; }
}

// ---------------------------------------------------------------------------
// Edge kernel: edge GVP + scatter-add into g_agg / g_cnt.
// 64 edges per block, 256 threads. Register-blocked GEMV:
//   warp wg handles 8 edges, lane tx handles 4 contiguous outputs (float4).
// ---------------------------------------------------------------------------
__global__ __launch_bounds__(256) void edge_kernel(
    const float* __restrict__ edge_s, const float* __restrict__ edge_v,
    const int* __restrict__ edge_index,
    const float* __restrict__ bes, const float* __restrict__ wev,
    const float* __restrict__ bev, int E)
{
    __shared__ float4 wsh[32 * 32];        // wesT as float4 [k][32]
    __shared__ float  es_sh[TE * 32];
    __shared__ float  ev_sh[TE * 3];
    __shared__ int    dst_sh[TE];
    __shared__ float  gate_sh[TE * 16];
    __shared__ float  bes_sh[128];
    __shared__ float  wev_sh[144];
    __shared__ float  bev_sh[48];

    const int tid = threadIdx.x;
    const int e0  = blockIdx.x * TE;
    const int nE  = min(TE, E - e0);

    {
        const float4* w4 = (const float4*)g_wesT;
        for (int i = tid; i < 1024; i += 256) wsh[i] = w4[i];
    }
    {
        const float4* s4 = (const float4*)(edge_s + (size_t)e0 * 32);
        float4* d4 = (float4*)es_sh;
        for (int i = tid; i < TE * 8; i += 256)
            if ((i >> 3) < nE) d4[i] = s4[i];
    }
    if (tid < TE * 3) { int e = tid / 3; ev_sh[tid] = (e < nE) ? edge_v[(size_t)e0 * 3 + tid] : 0.f; }
    if (tid < TE)     dst_sh[tid] = (tid < nE) ? edge_index[E + e0 + tid] : 0;
    if (tid < 128)    bes_sh[tid] = bes[tid];
    if (tid < 144)    wev_sh[tid] = wev[tid];
    if (tid < 48)     bev_sh[tid] = bev[tid];
    __syncthreads();

    const int tx = tid & 31;
    const int wg = tid >> 5;

    float4 acc[8];
#pragma unroll
    for (int j = 0; j < 8; j++) acc[j] = make_float4(0.f, 0.f, 0.f, 0.f);

#pragma unroll 4
    for (int k = 0; k < 32; k++) {
        float4 w = wsh[k * 32 + tx];
#pragma unroll
        for (int j = 0; j < 8; j++) {
            float e = es_sh[(wg * 8 + j) * 32 + k];    // warp-uniform broadcast
            acc[j].x = fmaf(w.x, e, acc[j].x);
            acc[j].y = fmaf(w.y, e, acc[j].y);
            acc[j].z = fmaf(w.z, e, acc[j].z);
            acc[j].w = fmaf(w.w, e, acc[j].w);
        }
    }

    const float4 bb = ((const float4*)bes_sh)[tx];
#pragma unroll
    for (int j = 0; j < 8; j++) {
        int el = wg * 8 + j;
        if (el >= nE) break;
        float4 s;
        s.x = acc[j].x + bb.x; s.y = acc[j].y + bb.y;
        s.z = acc[j].z + bb.z; s.w = acc[j].w + bb.w;
        s.x *= sigf(s.x); s.y *= sigf(s.y); s.z *= sigf(s.z); s.w *= sigf(s.w); // silu
        if (tx < 4) {  // gate = sigmoid(silu(out)[:16])
            gate_sh[el * 16 + 4 * tx + 0] = sigf(s.x);
            gate_sh[el * 16 + 4 * tx + 1] = sigf(s.y);
            gate_sh[el * 16 + 4 * tx + 2] = sigf(s.z);
            gate_sh[el * 16 + 4 * tx + 3] = sigf(s.w);
        }
        red4(g_agg + (size_t)dst_sh[el] * 176 + 4 * tx, s);
    }
    if (tid < nE) atomicAdd(&g_cnt[dst_sh[tid]], 1.f);
    __syncthreads();

    // vector part: 12 float4-quads per edge (48 outputs)
    for (int p = tid; p < TE * 12; p += 256) {
        int el = p / 12;
        if (el >= nE) continue;
        int q = p % 12;
        float e0v = ev_sh[el * 3 + 0], e1v = ev_sh[el * 3 + 1], e2v = ev_sh[el * 3 + 2];
        float4 v; float* vp = (float*)&v;
#pragma unroll
        for (int i = 0; i < 4; i++) {
            int o = 4 * q + i;
            float val = fmaf(wev_sh[o * 3 + 0], e0v,
                        fmaf(wev_sh[o * 3 + 1], e1v,
                        fmaf(wev_sh[o * 3 + 2], e2v, bev_sh[o])));
            vp[i] = val * gate_sh[el * 16 + o / 3];
        }
        red4(g_agg + (size_t)dst_sh[el] * 176 + 128 + 4 * q, v);
    }
}

// ---------------------------------------------------------------------------
// Node kernel: LN + vnorm + scatter-mean consume + node GVP + residuals.
// 32 nodes per block, 256 threads. Both 128x128 weight matrices in SMEM.
// ---------------------------------------------------------------------------
#define NODE_SMEM_FLOATS 50400

__global__ __launch_bounds__(256) void node_kernel(
    const float* __restrict__ node_s, const float* __restrict__ node_v,
    const float* __restrict__ ln_g, const float* __restrict__ ln_b,
    const float* __restrict__ bns, const float* __restrict__ brs,
    const float* __restrict__ bnv, const float* __restrict__ brv,
    float* __restrict__ out, int Nn)
{
    extern __shared__ float sm[];
    float* wST  = sm;                 // 32768
    float* wVT  = wST + 32768;        // 4608
    float* sn   = wVT + 4608;         // 4096  (raw -> s_n -> res_s)
    float* xs   = sn + 4096;          // 4096  (x_s  -> silu(out_pre))
    float* vn   = xs + 4096;          // 1536  (raw -> v_n)
    float* xv   = vn + 1536;          // 1536  (x_v)
    float* gate = xv + 1536;          // 512
    float* lng  = gate + 512;         // 128
    float* lnb  = lng + 128;          // 128
    float* bnsS = lnb + 128;          // 128
    float* brsS = bnsS + 128;         // 128
    float* bnvS = brsS + 128;         // 48
    float* brvS = bnvS + 48;          // 48

    const int tid = threadIdx.x;
    const int n0  = blockIdx.x * 32;
    const int nN  = min(32, Nn - n0);

    {
        float4* d = (float4*)wST; const float4* s = (const float4*)g_wST;
        for (int i = tid; i < 8192; i += 256) d[i] = s[i];
    }
    for (int i = tid; i < 4608; i += 256) wVT[i] = g_wVT[i];
    if (tid < 128) { lng[tid] = ln_g[tid]; lnb[tid] = ln_b[tid];
                     bnsS[tid] = bns[tid]; brsS[tid] = brs[tid]; }
    if (tid < 48)  { bnvS[tid] = bnv[tid]; brvS[tid] = brv[tid]; }
    for (int i = tid; i < 4096; i += 256)
        sn[i] = (i < nN * 128) ? node_s[(size_t)n0 * 128 + i] : 0.f;
    for (int i = tid; i < 1536; i += 256)
        vn[i] = (i < nN * 48) ? node_v[(size_t)n0 * 48 + i] : 0.f;
    __syncthreads();

    // --- LayerNorm + vector norm + aggregate consume: warp w -> nodes 4w..4w+3
    const int lane = tid & 31, w = tid >> 5;
    for (int q = 0; q < 4; q++) {
        int r = w * 4 + q;
        int n = n0 + r;
        const float* row = sn + r * 128;
        float a = row[lane] + row[lane + 32] + row[lane + 64] + row[lane + 96];
#pragma unroll
        for (int o = 16; o; o >>= 1) a += __shfl_xor_sync(0xffffffffu, a, o);
        float mu = a * (1.f / 128.f);
        float d0 = row[lane] - mu, d1 = row[lane + 32] - mu;
        float d2 = row[lane + 64] - mu, d3 = row[lane + 96] - mu;
        float vv = d0 * d0 + d1 * d1 + d2 * d2 + d3 * d3;
#pragma unroll
        for (int o = 16; o; o >>= 1) vv += __shfl_xor_sync(0xffffffffu, vv, o);
        float rs = rsqrtf(vv * (1.f / 128.f) + 1e-5f);

        const float* vrow = vn + r * 48;
        float x0 = vrow[lane];
        float x1 = (lane < 16) ? vrow[32 + lane] : 0.f;
        float sq = x0 * x0 + x1 * x1;
#pragma unroll
        for (int o = 16; o; o >>= 1) sq += __shfl_xor_sync(0xffffffffu, sq, o);
        float vr = rsqrtf(sq * (1.f / 16.f) + 1e-8f);

        float invden = 0.f;
        const float* aggr = g_agg + (size_t)n * 176;
        if (r < nN) invden = 1.f / fmaxf(g_cnt[n], 1.f);

#pragma unroll
        for (int jj = 0; jj < 4; jj++) {
            int c = lane + 32 * jj;
            float x = (row[c] - mu) * rs * lng[c] + lnb[c];
            sn[r * 128 + c] = x;
            float xa = x;
            if (r < nN) xa = x + aggr[c] * invden;
            xs[r * 128 + c] = xa;
        }
        {
            float x = x0 * vr;
            vn[r * 48 + lane] = x;
            float xa = x;
            if (r < nN) xa = x + aggr[128 + lane] * invden;
            xv[r * 48 + lane] = xa;
            if (lane < 16) {
                float y = x1 * vr;
                vn[r * 48 + 32 + lane] = y;
                float ya = y;
                if (r < nN) ya = y + aggr[128 + 32 + lane] * invden;
                xv[r * 48 + 32 + lane] = ya;
            }
        }
    }
    __syncthreads();

    // --- dual GEMM: [32,128] x [128,256]. og<32 -> wns(x_s), og>=32 -> wrs(s_n)
    const int og = tid & 63;
    const int ng = tid >> 6;
    const float* xin = (og < 32) ? xs : sn;
    const float4* w4 = (const float4*)wST;
    float4 acc[8];
#pragma unroll
    for (int j = 0; j < 8; j++) acc[j] = make_float4(0.f, 0.f, 0.f, 0.f);

#pragma unroll 4
    for (int k = 0; k < 128; k++) {
        float4 wv = w4[k * 64 + og];
#pragma unroll
        for (int j = 0; j < 8; j++) {
            float x = xin[(ng * 8 + j) * 128 + k];
            acc[j].x = fmaf(wv.x, x, acc[j].x);
            acc[j].y = fmaf(wv.y, x, acc[j].y);
            acc[j].z = fmaf(wv.z, x, acc[j].z);
            acc[j].w = fmaf(wv.w, x, acc[j].w);
        }
    }
    __syncthreads();   // everyone done reading xs/sn before we overwrite them

    if (og < 32) {
        float4 b = ((const float4*)bnsS)[og];
#pragma unroll
        for (int j = 0; j < 8; j++) {
            int r = ng * 8 + j;
            float4 s = acc[j];
            s.x += b.x; s.y += b.y; s.z += b.z; s.w += b.w;
            s.x *= sigf(s.x); s.y *= sigf(s.y); s.z *= sigf(s.z); s.w *= sigf(s.w);
            if (og < 4) {
                gate[r * 16 + 4 * og + 0] = sigf(s.x);
                gate[r * 16 + 4 * og + 1] = sigf(s.y);
                gate[r * 16 + 4 * og + 2] = sigf(s.z);
                gate[r * 16 + 4 * og + 3] = sigf(s.w);
            }
            ((float4*)xs)[r * 32 + og] = s;
        }
    } else {
        float4 b = ((const float4*)brsS)[og - 32];
#pragma unroll
        for (int j = 0; j < 8; j++) {
            int r = ng * 8 + j;
            float4 s = acc[j];
            s.x += b.x; s.y += b.y; s.z += b.z; s.w += b.w;
            ((float4*)sn)[r * 32 + (og - 32)] = s;
        }
    }
    __syncthreads();

    // scalar output: silu(out_pre) + residual
    for (int i = tid; i < nN * 128; i += 256)
        out[(size_t)n0 * 128 + i] = xs[i] + sn[i];

    // vector output: (x_v @ wnv^T + bnv) * gate + (v_n @ wrv^T + brv)
    for (int p = tid; p < nN * 48; p += 256) {
        int r = p / 48, o = p % 48;
        const float* xvr = xv + r * 48;
        const float* vnr = vn + r * 48;
        float a = 0.f, bq = 0.f;
#pragma unroll 4
        for (int k = 0; k < 48; k++) {
            a  = fmaf(xvr[k], wVT[k * 96 + o],      a);
            bq = fmaf(vnr[k], wVT[k * 96 + 48 + o], bq);
        }
        float val = (a + bnvS[o]) * gate[r * 16 + o / 3] + bq + brvS[o];
        out[(size_t)Nn * 128 + (size_t)n0 * 48 + p] = val;
    }
}

// ---------------------------------------------------------------------------
extern "C" void kernel_launch(void* const* d_in, const int* in_sizes, int n_in,
                              void* d_out, int out_size)
{
    const float* node_s = (const float*)d_in[0];
    const float* node_v = (const float*)d_in[1];
    const int*   ei     = (const int*)  d_in[2];
    const float* edge_s = (const float*)d_in[3];
    const float* edge_v = (const float*)d_in[4];
    const float* ln_g   = (const float*)d_in[5];
    const float* ln_b   = (const float*)d_in[6];
    const float* wes    = (const float*)d_in[7];
    const float* bes    = (const float*)d_in[8];
    const float* wev    = (const float*)d_in[9];
    const float* bev    = (const float*)d_in[10];
    const float* wns    = (const float*)d_in[11];
    const float* bns    = (const float*)d_in[12];
    const float* wnv    = (const float*)d_in[13];
    const float* bnv    = (const float*)d_in[14];
    const float* wrs    = (const float*)d_in[15];
    const float* brs    = (const float*)d_in[16];
    const float* wrv    = (const float*)d_in[17];
    const float* brv    = (const float*)d_in[18];

    const int N = in_sizes[0] / 128;
    const int E = in_sizes[3] / 32;

    void* aggp; void* cntp;
    cudaGetSymbolAddress(&aggp, g_agg);
    cudaGetSymbolAddress(&cntp, g_cnt);
    cudaMemsetAsync(aggp, 0, (size_t)N * 176 * sizeof(float), 0);
    cudaMemsetAsync(cntp, 0, (size_t)N * sizeof(float), 0);

    cudaFuncSetAttribute(node_kernel, cudaFuncAttributeMaxDynamicSharedMemorySize,
                         NODE_SMEM_FLOATS * sizeof(float));

    prep_kernel<<<64, 256>>>(wes, wns, wrs, wnv, wrv);
    edge_kernel<<<(E + TE - 1) / TE, 256>>>(edge_s, edge_v, ei, bes, wev, bev, E);
    node_kernel<<<(N + 31) / 32, 256, NODE_SMEM_FLOATS * sizeof(float)>>>(
        node_s, node_v, ln_g, ln_b, bns, brs, bnv, brv, (float*)d_out, N);
}